// round 17
// baseline (speedup 1.0000x reference)
#include <cuda_runtime.h>
#include <cuda_fp16.h>
#include <cstdint>

// FastGaussian2D as ONE separable GEMM.
//   alpha[p=(y,x), n] = Ey[n][y] * norm_n * Ex[n][x],  exp separable.
//   out[y,x,c] = clip( D[y][4x+c] / max(D[y][4x+3], 1e-8), 0, 1 )
//   where D = Ey^T (256x2048) @ B (2048x1024),  B[n][4x+c] = w_nc * Ex[n][x],
//   channel-interleaved N so each warp quad owns whole pixels.
//
// Kernel 1 (prep): writes Ey and B DIRECTLY in mma.sync m16n8k16 fragment
//   layout (we produce both operands, so the GEMM needs no smem/ldmatrix).
//   Precision: fp32 accum; Ey f16 rounding cancels in the image/alpha ratio
//   (identical factor in numerator & denominator); B rounds q=norm*Ex to f16
//   FIRST, then multiplies by color and rounds -> per-term ratio error <=2^-11.
// Kernel 2 (gemm): 128 blocks (Mtile32 x Ntile64), 8 warps = 4 positions x
//   2-way K-split; 256 HMMA/warp; smem K-reduction; fused epilogue divides by
//   alpha (2 shfls) and writes d_out. No atomics, no global state, trivially
//   graph-replay safe.

#define KDIM 2048          // gaussians (K)
#define MDIM 256           // image rows (M)
#define NDIM 1024          // 4*x + c   (N)
#define KT   128           // k-tiles of 16
#define LOG2E 1.4426950408889634f
#define PI_F  3.14159265358979323846f

typedef unsigned long long ull;

// fragment-layout operand storage
__device__ uint4 gAF[16 * KT * 32];      // A frags: [mt][kt][lane] -> 1 MB
__device__ uint2 gBF[128 * KT * 32];     // B frags: [nt][kt][lane] -> 4 MB

__device__ __forceinline__ float ex2f(float x) {
    float y; asm("ex2.approx.ftz.f32 %0, %1;" : "=f"(y) : "f"(x)); return y;
}
__device__ __forceinline__ uint32_t packh2(float a, float b) {
    __half2 h = __halves2half2(__float2half_rn(a), __float2half_rn(b));
    return *reinterpret_cast<uint32_t*>(&h);
}

// ---------------------------------------------------------------- prep
// warp w < 2048            -> A-fragment (mt = w>>7, kt = w&127)
// warp w in [2048, 18432)  -> B-fragment (idx = w-2048: nt = idx>>7, kt = idx&127)
__global__ void fg_prep(const float* __restrict__ pos,
                        const float* __restrict__ lsc,
                        const float* __restrict__ col,
                        const float* __restrict__ lop, int N) {
    const int w    = (blockIdx.x * blockDim.x + threadIdx.x) >> 5;
    const int lane = threadIdx.x & 31;
    const int tg   = lane & 3;        // thread-in-group
    const int grp  = lane >> 2;       // group id (row for A, col for B)
    if (w >= 18432) return;

    const int kcol[4] = { tg * 2, tg * 2 + 1, tg * 2 + 8, tg * 2 + 9 };

    if (w < 2048) {
        // ---- A fragment: Ey[y][k], rows y (M), cols k (K), row-major
        const int mt = w >> 7, kt = w & 127;
        const int kbase = kt * 16;
        float v[4][2];
        #pragma unroll
        for (int j = 0; j < 4; ++j) {
            const int k = kbase + kcol[j];
            if (k < N) {
                const float py = pos[2*k + 1];
                const float sy = fmaxf(__expf(lsc[2*k + 1]), 0.1f);
                const float nayl = -0.5f * LOG2E / (sy * sy);
                #pragma unroll
                for (int r = 0; r < 2; ++r) {
                    const float dy = (float)(mt * 16 + grp + r * 8) - py;
                    v[j][r] = ex2f(nayl * dy * dy);
                }
            } else { v[j][0] = 0.f; v[j][1] = 0.f; }
        }
        uint4 a;
        a.x = packh2(v[0][0], v[1][0]);   // row g,   cols 2tg, 2tg+1
        a.y = packh2(v[0][1], v[1][1]);   // row g+8, cols 2tg, 2tg+1
        a.z = packh2(v[2][0], v[3][0]);   // row g,   cols +8
        a.w = packh2(v[2][1], v[3][1]);   // row g+8, cols +8
        gAF[w * 32 + lane] = a;
    } else {
        // ---- B fragment: B[k][n], col-major n: lane grp = n-offset, k rows
        const int idx = w - 2048;
        const int nt = idx >> 7, kt = idx & 127;
        const int n = nt * 8 + grp;
        const int x = n >> 2, c = n & 3;
        const int kbase = kt * 16;
        __half hv[4];
        #pragma unroll
        for (int j = 0; j < 4; ++j) {
            const int k = kbase + kcol[j];
            if (k < N) {
                const float px = pos[2*k];
                const float sx = fmaxf(__expf(lsc[2*k]),   0.1f);
                const float sy = fmaxf(__expf(lsc[2*k+1]), 0.1f);
                const float opac = __expf(lop[k]);
                const float norm = opac / (2.0f * PI_F * sx * sy);
                const float naxl = -0.5f * LOG2E / (sx * sx);
                const float dx = (float)x - px;
                const float q  = norm * ex2f(naxl * dx * dx);
                const __half qh = __float2half_rn(q);     // round q FIRST
                if (c < 3) hv[j] = __float2half_rn(__half2float(qh) * col[3*k + c]);
                else       hv[j] = qh;                    // alpha column
            } else hv[j] = __float2half_rn(0.f);
        }
        uint2 b;
        {
            __half2 b0 = __halves2half2(hv[0], hv[1]);    // k rows 2tg, 2tg+1
            __half2 b1 = __halves2half2(hv[2], hv[3]);    // k rows +8
            b.x = *reinterpret_cast<uint32_t*>(&b0);
            b.y = *reinterpret_cast<uint32_t*>(&b1);
        }
        gBF[idx * 32 + lane] = b;
    }
}

// ---------------------------------------------------------------- gemm + epilogue
__device__ __forceinline__ void hmma(float acc[4], uint4 a, uint2 b) {
    asm volatile(
        "mma.sync.aligned.m16n8k16.row.col.f32.f16.f16.f32 "
        "{%0,%1,%2,%3}, {%4,%5,%6,%7}, {%8,%9}, {%0,%1,%2,%3};"
        : "+f"(acc[0]), "+f"(acc[1]), "+f"(acc[2]), "+f"(acc[3])
        : "r"(a.x), "r"(a.y), "r"(a.z), "r"(a.w), "r"(b.x), "r"(b.y));
}

__global__ void __launch_bounds__(256)
fg_gemm(float* __restrict__ out) {
    __shared__ float sred[4][32][16];   // ksplit partials: [pos][lane][j*4+r]

    const int lane = threadIdx.x & 31;
    const int warp = threadIdx.x >> 5;
    const int tg   = lane & 3;
    const int grp  = lane >> 2;

    const int mb = blockIdx.x & 7;      // 8 m-blocks (Mtile 32)
    const int nb = blockIdx.x >> 3;     // 16 n-blocks (Ntile 64)

    const int ws   = warp & 1;          // k-split half
    const int pos  = warp >> 1;         // 0..3
    const int wm   = pos >> 1;          // 0..1
    const int wn   = pos & 1;           // 0..1
    const int mt     = mb * 2 + wm;
    const int ntbase = nb * 8 + wn * 4;

    const uint4* Ap = gAF + mt * KT * 32 + lane;
    const uint2* Bp0 = gBF + (ntbase + 0) * KT * 32 + lane;
    const uint2* Bp1 = gBF + (ntbase + 1) * KT * 32 + lane;
    const uint2* Bp2 = gBF + (ntbase + 2) * KT * 32 + lane;
    const uint2* Bp3 = gBF + (ntbase + 3) * KT * 32 + lane;

    float acc[4][4] = {};

    const int k0 = ws * (KT / 2);
    #pragma unroll 4
    for (int kt = k0; kt < k0 + KT / 2; ++kt) {
        const uint4 a  = Ap [kt * 32];
        const uint2 b0 = Bp0[kt * 32];
        const uint2 b1 = Bp1[kt * 32];
        const uint2 b2 = Bp2[kt * 32];
        const uint2 b3 = Bp3[kt * 32];
        hmma(acc[0], a, b0);
        hmma(acc[1], a, b1);
        hmma(acc[2], a, b2);
        hmma(acc[3], a, b3);
    }

    // combine the two k-halves
    if (ws == 1) {
        #pragma unroll
        for (int j = 0; j < 4; ++j)
            #pragma unroll
            for (int r = 0; r < 4; ++r)
                sred[pos][lane][j * 4 + r] = acc[j][r];
    }
    __syncthreads();
    if (ws == 0) {
        #pragma unroll
        for (int j = 0; j < 4; ++j)
            #pragma unroll
            for (int r = 0; r < 4; ++r)
                acc[j][r] += sred[pos][lane][j * 4 + r];

        // epilogue: D layout per frag j: cols n = ntj*8 + 2tg + {0,1};
        // rows y = mt*16 + grp (c0,c1) and +8 (c2,c3). alpha at n%4==3
        // (quad lanes tg1 / tg3, register c1/c3).
        const int srcl = (lane & ~3) | ((tg < 2) ? 1 : 3);
        #pragma unroll
        for (int j = 0; j < 4; ++j) {
            const float aG  = __shfl_sync(0xFFFFFFFFu, acc[j][1], srcl);
            const float aG8 = __shfl_sync(0xFFFFFFFFu, acc[j][3], srcl);
            const float invG  = 1.0f / fmaxf(aG,  1e-8f);
            const float invG8 = 1.0f / fmaxf(aG8, 1e-8f);

            const int ntj = ntbase + j;
            const int x   = ntj * 2 + (tg >> 1);
            const int y   = mt * 16 + grp;
            const int ch0 = (2 * tg) & 3;           // 0 or 2
            const int ch1 = ch0 + 1;                // 1 or 3

            out[(y * 256 + x) * 3 + ch0] = __saturatef(acc[j][0] * invG);
            if (ch1 < 3)
                out[(y * 256 + x) * 3 + ch1] = __saturatef(acc[j][1] * invG);
            out[((y + 8) * 256 + x) * 3 + ch0] = __saturatef(acc[j][2] * invG8);
            if (ch1 < 3)
                out[((y + 8) * 256 + x) * 3 + ch1] = __saturatef(acc[j][3] * invG8);
        }
    }
}

// ---------------------------------------------------------------- launch
extern "C" void kernel_launch(void* const* d_in, const int* in_sizes, int n_in,
                              void* d_out, int out_size) {
    const float* pos = (const float*)d_in[1];
    const float* lsc = (const float*)d_in[2];
    const float* col = (const float*)d_in[3];
    const float* lop = (const float*)d_in[4];
    float* out = (float*)d_out;

    int N = in_sizes[1] / 2;
    if (N > KDIM) N = KDIM;

    fg_prep<<<2304, 256>>>(pos, lsc, col, lop, N);   // 18432 warps
    fg_gemm<<<128, 256>>>(out);
}